// round 9
// baseline (speedup 1.0000x reference)
#include <cuda_runtime.h>

#define NN 50000
#define NE 600000
#define C  128
#define NB ((NN + 255) / 256)   // 196 scan blocks

// ---------------- scratch (static __device__, zero-initialized at load) ----------------
__device__ int   g_cnt[NN];      // stays zero between pipeline runs (bucket re-zeros)
__device__ int   g_off[NN + 1];
__device__ int   g_cur[NN];
__device__ int   g_bsum[NB];
__device__ int   g_csrc[NE];
__device__ float g_dis[NN];
__device__ float g_t[NN * C];
__device__ float g_skip[NN * C];

// ---------------- f32x2 packed-FMA helpers (sm_100) ----------------
__device__ __forceinline__ unsigned long long pk2(float lo, float hi) {
    unsigned long long r;
    asm("mov.b64 %0, {%1, %2};" : "=l"(r) : "f"(lo), "f"(hi));
    return r;
}
__device__ __forceinline__ void fma2(unsigned long long& d, unsigned long long a,
                                     unsigned long long b) {
    asm("fma.rn.f32x2 %0, %1, %2, %0;" : "+l"(d) : "l"(a), "l"(b));
}
__device__ __forceinline__ float2 unpk2(unsigned long long v) {
    float2 f;
    asm("mov.b64 {%0, %1}, %2;" : "=f"(f.x), "=f"(f.y) : "l"(v));
    return f;
}

// ---------------- CSR build ----------------
__global__ void k_deg_count(const int4* __restrict__ dst4) {
    int i = blockIdx.x * blockDim.x + threadIdx.x;
    if (i < NE / 4) {
        int4 d = dst4[i];
        atomicAdd(&g_cnt[d.x], 1);
        atomicAdd(&g_cnt[d.y], 1);
        atomicAdd(&g_cnt[d.z], 1);
        atomicAdd(&g_cnt[d.w], 1);
    }
}
__global__ void k_scan_a() {
    __shared__ int s[256];
    int tid = threadIdx.x;
    int i = blockIdx.x * 256 + tid;
    int v = (i < NN) ? g_cnt[i] : 0;
    s[tid] = v;
    __syncthreads();
    for (int d = 1; d < 256; d <<= 1) {
        int tv = 0;
        if (tid >= d) tv = s[tid - d];
        __syncthreads();
        if (tid >= d) s[tid] += tv;
        __syncthreads();
    }
    if (i < NN) g_off[i] = s[tid] - v;  // exclusive, block-local
    if (tid == 255) g_bsum[blockIdx.x] = s[255];
}
__global__ void k_scan_c() {
    __shared__ int red[256];
    int tid = threadIdx.x, bid = blockIdx.x;
    red[tid] = (tid < bid && tid < NB) ? g_bsum[tid] : 0;
    __syncthreads();
    for (int d = 128; d > 0; d >>= 1) {
        if (tid < d) red[tid] += red[tid + d];
        __syncthreads();
    }
    int base = red[0];
    int i = bid * 256 + tid;
    if (i < NN) {
        int o = g_off[i] + base;
        g_off[i] = o;
        g_cur[i] = o;
        g_dis[i] = rsqrtf((float)(g_cnt[i] + 1));  // +1 self loop
    }
    if (i == 0) g_off[NN] = NE;
}
__global__ void k_bucket(const int4* __restrict__ src4, const int4* __restrict__ dst4) {
    int i = blockIdx.x * blockDim.x + threadIdx.x;
    if (i < NE / 4) {
        int4 s = src4[i];
        int4 d = dst4[i];
        int p;
        p = atomicAdd(&g_cur[d.x], 1); g_csrc[p] = s.x;
        p = atomicAdd(&g_cur[d.y], 1); g_csrc[p] = s.y;
        p = atomicAdd(&g_cur[d.z], 1); g_csrc[p] = s.z;
        p = atomicAdd(&g_cur[d.w], 1); g_csrc[p] = s.w;
    }
    if (i < NN / 4) ((int4*)g_cnt)[i] = make_int4(0, 0, 0, 0);
}

// ---------------- GEMM: out[64 rows/block] = in @ W (+bias) ----------------
// Lane-contiguous packed-W smem (conflict-free; see R6 comment) + explicit
// software pipelining: w double-buffered one kq ahead (128 FMA-cycles cover the
// 29-cyc LDS latency), x broadcast ping-ponged one row ahead.
__global__ __launch_bounds__(256, 2) void k_gemm(const float* __restrict__ in,
                                                 const float* __restrict__ W,
                                                 const float* __restrict__ bias,
                                                 float* __restrict__ out) {
    extern __shared__ float sm[];
    unsigned long long* wp = (unsigned long long*)sm;  // [64][128] u64, 64KB
    float* xs = sm + 16384;                            // [64][128], 32KB
    int tid = threadIdx.x;
    int row0 = blockIdx.x * 64;

    // pack W: group g = (kp, l); cols 4l..4l+3 of k-rows 2kp, 2kp+1
    for (int g = tid; g < (C / 2) * 32; g += 256) {  // 2048 groups
        int kp = g >> 5;
        int l = g & 31;
        float4 va = *(const float4*)&W[(2 * kp) * C + 4 * l];
        float4 vb = *(const float4*)&W[(2 * kp + 1) * C + 4 * l];
        ulonglong2 pA, pB;
        pA.x = pk2(va.x, vb.x);
        pA.y = pk2(va.y, vb.y);
        pB.x = pk2(va.z, vb.z);
        pB.y = pk2(va.w, vb.w);
        *(ulonglong2*)&wp[kp * 128 + 2 * l] = pA;        // byte l*16
        *(ulonglong2*)&wp[kp * 128 + 64 + 2 * l] = pB;   // byte 512 + l*16
    }
    for (int i = tid; i < 64 * C / 4; i += 256) {
        int r = i >> 5;
        int gr = row0 + r;
        ((float4*)xs)[i] = (gr < NN) ? ((const float4*)in)[gr * 32 + (i & 31)]
                                     : make_float4(0.f, 0.f, 0.f, 0.f);
    }
    __syncthreads();

    int warp = tid >> 5, lane = tid & 31;
    int r0 = warp * 8;   // 8 warps x 8 rows
    int c0 = lane * 4;   // 32 lanes x 4 cols

    unsigned long long acc[8][4];
#pragma unroll
    for (int i = 0; i < 8; i++)
#pragma unroll
        for (int j = 0; j < 4; j++) acc[i][j] = 0ull;

    const unsigned long long* wl = wp + 2 * lane;  // lane base into packed W
    const float* xb = xs + r0 * C;                 // warp's x rows

    // prologue: w for kq=0, x for row 0
    ulonglong2 wc0 = *(const ulonglong2*)&wl[0];
    ulonglong2 wc1 = *(const ulonglong2*)&wl[64];
    ulonglong2 wc2 = *(const ulonglong2*)&wl[128];
    ulonglong2 wc3 = *(const ulonglong2*)&wl[192];
    ulonglong2 xc  = *(const ulonglong2*)&xb[0];

#pragma unroll 1
    for (int kq = 0; kq < C / 4; kq++) {
        // prefetch next kq's w (kq=31 reads into xs region: in-bounds, unused)
        const unsigned long long* wn = wl + (kq + 1) * 256;
        ulonglong2 wn0 = *(const ulonglong2*)&wn[0];
        ulonglong2 wn1 = *(const ulonglong2*)&wn[64];
        ulonglong2 wn2 = *(const ulonglong2*)&wn[128];
        ulonglong2 wn3 = *(const ulonglong2*)&wn[192];
#pragma unroll
        for (int i = 0; i < 8; i++) {
            // prefetch next row's x (row i+1 this kq, or row 0 next kq)
            ulonglong2 xn = (i < 7)
                ? *(const ulonglong2*)&xb[(i + 1) * C + 4 * kq]
                : *(const ulonglong2*)&xb[4 * (kq + 1)];
            fma2(acc[i][0], xc.x, wc0.x);
            fma2(acc[i][1], xc.x, wc0.y);
            fma2(acc[i][2], xc.x, wc1.x);
            fma2(acc[i][3], xc.x, wc1.y);
            fma2(acc[i][0], xc.y, wc2.x);
            fma2(acc[i][1], xc.y, wc2.y);
            fma2(acc[i][2], xc.y, wc3.x);
            fma2(acc[i][3], xc.y, wc3.y);
            xc = xn;
        }
        wc0 = wn0; wc1 = wn1; wc2 = wn2; wc3 = wn3;
    }

    float4 bv = make_float4(0.f, 0.f, 0.f, 0.f);
    if (bias) bv = ((const float4*)bias)[lane];
#pragma unroll
    for (int i = 0; i < 8; i++) {
        int gr = row0 + r0 + i;
        if (gr < NN) {
            float2 p0 = unpk2(acc[i][0]);
            float2 p1 = unpk2(acc[i][1]);
            float2 p2 = unpk2(acc[i][2]);
            float2 p3 = unpk2(acc[i][3]);
            *(float4*)&out[gr * C + c0] =
                make_float4(p0.x + p0.y + bv.x, p1.x + p1.y + bv.y,
                            p2.x + p2.y + bv.z, p3.x + p3.y + bv.w);
        }
    }
}

// ---------------- CSR gather: one warp per node, edge loop unrolled x4 ----------------
__global__ __launch_bounds__(256) void k_gather(const float* __restrict__ t,
                                                const float* __restrict__ b,
                                                const float* __restrict__ a,
                                                float* __restrict__ skip_io,
                                                float* __restrict__ out, int mode) {
    int node = (blockIdx.x * 256 + threadIdx.x) >> 5;
    int lane = threadIdx.x & 31;
    if (node >= NN) return;

    float di = g_dis[node];
    float d2 = di * di;
    float4 bv = ((const float4*)b)[lane];
    float4 tv = ((const float4*)t)[node * 32 + lane];
    float4 acc = make_float4(bv.x + tv.x * d2, bv.y + tv.y * d2,
                             bv.z + tv.z * d2, bv.w + tv.w * d2);

    int beg = g_off[node], end = g_off[node + 1];
    for (int base = beg; base < end; base += 32) {
        int idx = base + lane;
        int s = 0;
        float w = 0.f;
        if (idx < end) {
            s = g_csrc[idx];
            w = g_dis[s] * di;
        }
        int cnt = min(32, end - base);
        int j = 0;
        for (; j + 4 <= cnt; j += 4) {
            int s0 = __shfl_sync(0xffffffffu, s, j);
            int s1 = __shfl_sync(0xffffffffu, s, j + 1);
            int s2 = __shfl_sync(0xffffffffu, s, j + 2);
            int s3 = __shfl_sync(0xffffffffu, s, j + 3);
            float w0 = __shfl_sync(0xffffffffu, w, j);
            float w1 = __shfl_sync(0xffffffffu, w, j + 1);
            float w2 = __shfl_sync(0xffffffffu, w, j + 2);
            float w3 = __shfl_sync(0xffffffffu, w, j + 3);
            float4 v0 = ((const float4*)t)[s0 * 32 + lane];
            float4 v1 = ((const float4*)t)[s1 * 32 + lane];
            float4 v2 = ((const float4*)t)[s2 * 32 + lane];
            float4 v3 = ((const float4*)t)[s3 * 32 + lane];
            acc.x += v0.x * w0; acc.y += v0.y * w0; acc.z += v0.z * w0; acc.w += v0.w * w0;
            acc.x += v1.x * w1; acc.y += v1.y * w1; acc.z += v1.z * w1; acc.w += v1.w * w1;
            acc.x += v2.x * w2; acc.y += v2.y * w2; acc.z += v2.z * w2; acc.w += v2.w * w2;
            acc.x += v3.x * w3; acc.y += v3.y * w3; acc.z += v3.z * w3; acc.w += v3.w * w3;
        }
        for (; j < cnt; j++) {
            int sj = __shfl_sync(0xffffffffu, s, j);
            float wj = __shfl_sync(0xffffffffu, w, j);
            float4 v = ((const float4*)t)[sj * 32 + lane];
            acc.x += v.x * wj; acc.y += v.y * wj; acc.z += v.z * wj; acc.w += v.w * wj;
        }
    }

    float4 av = ((const float4*)a)[lane];
    float4 p;
    p.x = acc.x >= 0.f ? acc.x : av.x * acc.x;
    p.y = acc.y >= 0.f ? acc.y : av.y * acc.y;
    p.z = acc.z >= 0.f ? acc.z : av.z * acc.z;
    p.w = acc.w >= 0.f ? acc.w : av.w * acc.w;

    if (mode == 0) {
        float4 sk = ((const float4*)skip_io)[node * 32 + lane];
        ((float4*)skip_io)[node * 32 + lane] =
            make_float4(sk.x + p.x, sk.y + p.y, sk.z + p.z, sk.w + p.w);
    } else {
        ((float4*)out)[node * 32 + lane] = p;
    }
}

extern "C" void kernel_launch(void* const* d_in, const int* in_sizes, int n_in,
                              void* d_out, int out_size) {
    const float* x  = (const float*)d_in[0];
    const int*   ei = (const int*)d_in[1];
    const float* W0 = (const float*)d_in[2];
    const float* b0 = (const float*)d_in[3];
    const float* W1 = (const float*)d_in[4];
    const float* b1 = (const float*)d_in[5];
    const float* Ws = (const float*)d_in[6];
    const float* bs = (const float*)d_in[7];
    const float* a  = (const float*)d_in[8];
    float* out = (float*)d_out;

    const int4* src4 = (const int4*)ei;
    const int4* dst4 = (const int4*)(ei + NE);

    float *t, *skip;
    cudaGetSymbolAddress((void**)&t, g_t);
    cudaGetSymbolAddress((void**)&skip, g_skip);

    const int GEMM_SMEM = (C * C + 64 * C) * 4;  // 96KB
    cudaFuncSetAttribute(k_gemm, cudaFuncAttributeMaxDynamicSharedMemorySize,
                         GEMM_SMEM);

    const int GEMM_GRID = (NN + 63) / 64;
    const int GATHER_GRID = (NN * 32 + 255) / 256;
    const int E4 = NE / 4;

    // 9 launches; index 3 (ncu capture slot) = first k_gemm
    k_deg_count<<<(E4 + 255) / 256, 256>>>(dst4);                 // 0
    k_scan_a<<<NB, 256>>>();                                      // 1
    k_scan_c<<<NB, 256>>>();                                      // 2

    k_gemm<<<GEMM_GRID, 256, GEMM_SMEM>>>(x, Ws, bs, skip);       // 3: skip = x@Ws+bs  [ncu]
    k_gemm<<<GEMM_GRID, 256, GEMM_SMEM>>>(x, W0, nullptr, t);     // 4: t = x@W0

    k_bucket<<<(E4 + 255) / 256, 256>>>(src4, dst4);              // 5 (also re-zeros g_cnt)
    k_gather<<<GATHER_GRID, 256>>>(t, b0, a, skip, nullptr, 0);   // 6: skip = u

    k_gemm<<<GEMM_GRID, 256, GEMM_SMEM>>>(skip, W1, nullptr, t);  // 7: t = u@W1
    k_gather<<<GATHER_GRID, 256>>>(t, b1, a, nullptr, out, 1);    // 8: out
}

// round 10
// speedup vs baseline: 1.0784x; 1.0784x over previous
#include <cuda_runtime.h>

#define NN 50000
#define NE 600000
#define C  128
#define NB ((NN + 255) / 256)   // 196 scan blocks

// ---------------- scratch (static __device__, zero-initialized at load) ----------------
__device__ int   g_cnt[NN];      // stays zero between pipeline runs (bucket re-zeros)
__device__ int   g_off[NN + 1];
__device__ int   g_cur[NN];
__device__ int   g_bsum[NB];
__device__ int   g_csrc[NE];
__device__ float g_dis[NN];
__device__ float g_t[NN * C];
__device__ float g_skip[NN * C];

// ---------------- f32x2 packed-FMA helpers (sm_100) ----------------
__device__ __forceinline__ unsigned long long pk2(float lo, float hi) {
    unsigned long long r;
    asm("mov.b64 %0, {%1, %2};" : "=l"(r) : "f"(lo), "f"(hi));
    return r;
}
__device__ __forceinline__ void fma2(unsigned long long& d, unsigned long long a,
                                     unsigned long long b) {
    asm("fma.rn.f32x2 %0, %1, %2, %0;" : "+l"(d) : "l"(a), "l"(b));
}
__device__ __forceinline__ float2 unpk2(unsigned long long v) {
    float2 f;
    asm("mov.b64 {%0, %1}, %2;" : "=f"(f.x), "=f"(f.y) : "l"(v));
    return f;
}

// ---------------- CSR build ----------------
__global__ void k_deg_count(const int4* __restrict__ dst4) {
    int i = blockIdx.x * blockDim.x + threadIdx.x;
    if (i < NE / 4) {
        int4 d = dst4[i];
        atomicAdd(&g_cnt[d.x], 1);
        atomicAdd(&g_cnt[d.y], 1);
        atomicAdd(&g_cnt[d.z], 1);
        atomicAdd(&g_cnt[d.w], 1);
    }
}
__global__ void k_scan_a() {
    __shared__ int s[256];
    int tid = threadIdx.x;
    int i = blockIdx.x * 256 + tid;
    int v = (i < NN) ? g_cnt[i] : 0;
    s[tid] = v;
    __syncthreads();
    for (int d = 1; d < 256; d <<= 1) {
        int tv = 0;
        if (tid >= d) tv = s[tid - d];
        __syncthreads();
        if (tid >= d) s[tid] += tv;
        __syncthreads();
    }
    if (i < NN) g_off[i] = s[tid] - v;  // exclusive, block-local
    if (tid == 255) g_bsum[blockIdx.x] = s[255];
}
__global__ void k_scan_c() {
    __shared__ int red[256];
    int tid = threadIdx.x, bid = blockIdx.x;
    red[tid] = (tid < bid && tid < NB) ? g_bsum[tid] : 0;
    __syncthreads();
    for (int d = 128; d > 0; d >>= 1) {
        if (tid < d) red[tid] += red[tid + d];
        __syncthreads();
    }
    int base = red[0];
    int i = bid * 256 + tid;
    if (i < NN) {
        int o = g_off[i] + base;
        g_off[i] = o;
        g_cur[i] = o;
        g_dis[i] = rsqrtf((float)(g_cnt[i] + 1));  // +1 self loop
    }
    if (i == 0) g_off[NN] = NE;
}
__global__ void k_bucket(const int4* __restrict__ src4, const int4* __restrict__ dst4) {
    int i = blockIdx.x * blockDim.x + threadIdx.x;
    if (i < NE / 4) {
        int4 s = src4[i];
        int4 d = dst4[i];
        int p;
        p = atomicAdd(&g_cur[d.x], 1); g_csrc[p] = s.x;
        p = atomicAdd(&g_cur[d.y], 1); g_csrc[p] = s.y;
        p = atomicAdd(&g_cur[d.z], 1); g_csrc[p] = s.z;
        p = atomicAdd(&g_cur[d.w], 1); g_csrc[p] = s.w;
    }
    if (i < NN / 4) ((int4*)g_cnt)[i] = make_int4(0, 0, 0, 0);
}

// ---------------- GEMM: out[64 rows/block] = in @ W (+bias) ----------------
// Lane-contiguous packed-W smem (conflict-free) + BATCHED operand loads:
// all 12 LDS.128 for a kq issue back-to-back (MLP=12) before the 64-FFMA2 block,
// so LDS latency is overlapped by load-level parallelism, not a carried pipeline.
__global__ __launch_bounds__(256, 2) void k_gemm(const float* __restrict__ in,
                                                 const float* __restrict__ W,
                                                 const float* __restrict__ bias,
                                                 float* __restrict__ out) {
    extern __shared__ float sm[];
    unsigned long long* wp = (unsigned long long*)sm;  // [64][128] u64, 64KB
    float* xs = sm + 16384;                            // [64][128], 32KB
    int tid = threadIdx.x;
    int row0 = blockIdx.x * 64;

    // pack W: group g = (kp, l); cols 4l..4l+3 of k-rows 2kp, 2kp+1
    for (int g = tid; g < (C / 2) * 32; g += 256) {  // 2048 groups
        int kp = g >> 5;
        int l = g & 31;
        float4 va = *(const float4*)&W[(2 * kp) * C + 4 * l];
        float4 vb = *(const float4*)&W[(2 * kp + 1) * C + 4 * l];
        ulonglong2 pA, pB;
        pA.x = pk2(va.x, vb.x);
        pA.y = pk2(va.y, vb.y);
        pB.x = pk2(va.z, vb.z);
        pB.y = pk2(va.w, vb.w);
        *(ulonglong2*)&wp[kp * 128 + 2 * l] = pA;        // byte l*16 (conflict-free)
        *(ulonglong2*)&wp[kp * 128 + 64 + 2 * l] = pB;   // byte 512 + l*16
    }
    for (int i = tid; i < 64 * C / 4; i += 256) {
        int r = i >> 5;
        int gr = row0 + r;
        ((float4*)xs)[i] = (gr < NN) ? ((const float4*)in)[gr * 32 + (i & 31)]
                                     : make_float4(0.f, 0.f, 0.f, 0.f);
    }
    __syncthreads();

    int warp = tid >> 5, lane = tid & 31;
    int r0 = warp * 8;   // 8 warps x 8 rows
    int c0 = lane * 4;   // 32 lanes x 4 cols

    unsigned long long acc[8][4];
#pragma unroll
    for (int i = 0; i < 8; i++)
#pragma unroll
        for (int j = 0; j < 4; j++) acc[i][j] = 0ull;

    const unsigned long long* wl = wp + 2 * lane;  // lane base into packed W
    const float* xb = xs + r0 * C;                 // warp's x rows

#pragma unroll 1
    for (int kq = 0; kq < C / 4; kq++) {  // 4 k's per iteration
        // --- batched loads: 4 w + 8 x LDS.128, all independent ---
        const unsigned long long* wk = wl + kq * 256;
        ulonglong2 w0 = *(const ulonglong2*)&wk[0];     // kp0, cols (4l,4l+1)
        ulonglong2 w1 = *(const ulonglong2*)&wk[64];    // kp0, cols (4l+2,4l+3)
        ulonglong2 w2 = *(const ulonglong2*)&wk[128];   // kp1, cols (4l,4l+1)
        ulonglong2 w3 = *(const ulonglong2*)&wk[192];   // kp1, cols (4l+2,4l+3)
        ulonglong2 xr[8];
#pragma unroll
        for (int i = 0; i < 8; i++)
            xr[i] = *(const ulonglong2*)&xb[i * C + 4 * kq];
        // --- 64 FFMA2 block ---
#pragma unroll
        for (int i = 0; i < 8; i++) {
            fma2(acc[i][0], xr[i].x, w0.x);
            fma2(acc[i][1], xr[i].x, w0.y);
            fma2(acc[i][2], xr[i].x, w1.x);
            fma2(acc[i][3], xr[i].x, w1.y);
            fma2(acc[i][0], xr[i].y, w2.x);
            fma2(acc[i][1], xr[i].y, w2.y);
            fma2(acc[i][2], xr[i].y, w3.x);
            fma2(acc[i][3], xr[i].y, w3.y);
        }
    }

    float4 bv = make_float4(0.f, 0.f, 0.f, 0.f);
    if (bias) bv = ((const float4*)bias)[lane];
#pragma unroll
    for (int i = 0; i < 8; i++) {
        int gr = row0 + r0 + i;
        if (gr < NN) {
            float2 p0 = unpk2(acc[i][0]);
            float2 p1 = unpk2(acc[i][1]);
            float2 p2 = unpk2(acc[i][2]);
            float2 p3 = unpk2(acc[i][3]);
            *(float4*)&out[gr * C + c0] =
                make_float4(p0.x + p0.y + bv.x, p1.x + p1.y + bv.y,
                            p2.x + p2.y + bv.z, p3.x + p3.y + bv.w);
        }
    }
}

// ---------------- CSR gather: one warp per node, edge loop unrolled x4 ----------------
__global__ __launch_bounds__(256) void k_gather(const float* __restrict__ t,
                                                const float* __restrict__ b,
                                                const float* __restrict__ a,
                                                float* __restrict__ skip_io,
                                                float* __restrict__ out, int mode) {
    int node = (blockIdx.x * 256 + threadIdx.x) >> 5;
    int lane = threadIdx.x & 31;
    if (node >= NN) return;

    float di = g_dis[node];
    float d2 = di * di;
    float4 bv = ((const float4*)b)[lane];
    float4 tv = ((const float4*)t)[node * 32 + lane];
    float4 acc = make_float4(bv.x + tv.x * d2, bv.y + tv.y * d2,
                             bv.z + tv.z * d2, bv.w + tv.w * d2);

    int beg = g_off[node], end = g_off[node + 1];
    for (int base = beg; base < end; base += 32) {
        int idx = base + lane;
        int s = 0;
        float w = 0.f;
        if (idx < end) {
            s = g_csrc[idx];
            w = g_dis[s] * di;
        }
        int cnt = min(32, end - base);
        int j = 0;
        for (; j + 4 <= cnt; j += 4) {
            int s0 = __shfl_sync(0xffffffffu, s, j);
            int s1 = __shfl_sync(0xffffffffu, s, j + 1);
            int s2 = __shfl_sync(0xffffffffu, s, j + 2);
            int s3 = __shfl_sync(0xffffffffu, s, j + 3);
            float w0 = __shfl_sync(0xffffffffu, w, j);
            float w1 = __shfl_sync(0xffffffffu, w, j + 1);
            float w2 = __shfl_sync(0xffffffffu, w, j + 2);
            float w3 = __shfl_sync(0xffffffffu, w, j + 3);
            float4 v0 = ((const float4*)t)[s0 * 32 + lane];
            float4 v1 = ((const float4*)t)[s1 * 32 + lane];
            float4 v2 = ((const float4*)t)[s2 * 32 + lane];
            float4 v3 = ((const float4*)t)[s3 * 32 + lane];
            acc.x += v0.x * w0; acc.y += v0.y * w0; acc.z += v0.z * w0; acc.w += v0.w * w0;
            acc.x += v1.x * w1; acc.y += v1.y * w1; acc.z += v1.z * w1; acc.w += v1.w * w1;
            acc.x += v2.x * w2; acc.y += v2.y * w2; acc.z += v2.z * w2; acc.w += v2.w * w2;
            acc.x += v3.x * w3; acc.y += v3.y * w3; acc.z += v3.z * w3; acc.w += v3.w * w3;
        }
        for (; j < cnt; j++) {
            int sj = __shfl_sync(0xffffffffu, s, j);
            float wj = __shfl_sync(0xffffffffu, w, j);
            float4 v = ((const float4*)t)[sj * 32 + lane];
            acc.x += v.x * wj; acc.y += v.y * wj; acc.z += v.z * wj; acc.w += v.w * wj;
        }
    }

    float4 av = ((const float4*)a)[lane];
    float4 p;
    p.x = acc.x >= 0.f ? acc.x : av.x * acc.x;
    p.y = acc.y >= 0.f ? acc.y : av.y * acc.y;
    p.z = acc.z >= 0.f ? acc.z : av.z * acc.z;
    p.w = acc.w >= 0.f ? acc.w : av.w * acc.w;

    if (mode == 0) {
        float4 sk = ((const float4*)skip_io)[node * 32 + lane];
        ((float4*)skip_io)[node * 32 + lane] =
            make_float4(sk.x + p.x, sk.y + p.y, sk.z + p.z, sk.w + p.w);
    } else {
        ((float4*)out)[node * 32 + lane] = p;
    }
}

extern "C" void kernel_launch(void* const* d_in, const int* in_sizes, int n_in,
                              void* d_out, int out_size) {
    const float* x  = (const float*)d_in[0];
    const int*   ei = (const int*)d_in[1];
    const float* W0 = (const float*)d_in[2];
    const float* b0 = (const float*)d_in[3];
    const float* W1 = (const float*)d_in[4];
    const float* b1 = (const float*)d_in[5];
    const float* Ws = (const float*)d_in[6];
    const float* bs = (const float*)d_in[7];
    const float* a  = (const float*)d_in[8];
    float* out = (float*)d_out;

    const int4* src4 = (const int4*)ei;
    const int4* dst4 = (const int4*)(ei + NE);

    float *t, *skip;
    cudaGetSymbolAddress((void**)&t, g_t);
    cudaGetSymbolAddress((void**)&skip, g_skip);

    const int GEMM_SMEM = (C * C + 64 * C) * 4;  // 96KB
    cudaFuncSetAttribute(k_gemm, cudaFuncAttributeMaxDynamicSharedMemorySize,
                         GEMM_SMEM);

    const int GEMM_GRID = (NN + 63) / 64;
    const int GATHER_GRID = (NN * 32 + 255) / 256;
    const int E4 = NE / 4;

    // 9 launches; index 3 (ncu capture slot) = first k_gemm
    k_deg_count<<<(E4 + 255) / 256, 256>>>(dst4);                 // 0
    k_scan_a<<<NB, 256>>>();                                      // 1
    k_scan_c<<<NB, 256>>>();                                      // 2

    k_gemm<<<GEMM_GRID, 256, GEMM_SMEM>>>(x, Ws, bs, skip);       // 3: skip = x@Ws+bs  [ncu]
    k_gemm<<<GEMM_GRID, 256, GEMM_SMEM>>>(x, W0, nullptr, t);     // 4: t = x@W0

    k_bucket<<<(E4 + 255) / 256, 256>>>(src4, dst4);              // 5 (also re-zeros g_cnt)
    k_gather<<<GATHER_GRID, 256>>>(t, b0, a, skip, nullptr, 0);   // 6: skip = u

    k_gemm<<<GEMM_GRID, 256, GEMM_SMEM>>>(skip, W1, nullptr, t);  // 7: t = u@W1
    k_gather<<<GATHER_GRID, 256>>>(t, b1, a, nullptr, out, 1);    // 8: out
}

// round 12
// speedup vs baseline: 1.2402x; 1.1500x over previous
#include <cuda_runtime.h>
#include <cuda_bf16.h>

#define NN 50000
#define NE 600000
#define C  128
#define NB ((NN + 255) / 256)   // 196 scan blocks

// ---------------- scratch (static __device__, zero-initialized at load) ----------------
__device__ int   g_cnt[NN];      // stays zero between pipeline runs (bucket re-zeros)
__device__ int   g_off[NN + 1];
__device__ int   g_cur[NN];
__device__ int   g_bsum[NB];
__device__ int   g_csrc[NE];
__device__ float g_dis[NN];
__device__ float g_t[NN * C];
__device__ float g_skip[NN * C];

// ---------------- CSR build ----------------
__global__ void k_deg_count(const int4* __restrict__ dst4) {
    int i = blockIdx.x * blockDim.x + threadIdx.x;
    if (i < NE / 4) {
        int4 d = dst4[i];
        atomicAdd(&g_cnt[d.x], 1);
        atomicAdd(&g_cnt[d.y], 1);
        atomicAdd(&g_cnt[d.z], 1);
        atomicAdd(&g_cnt[d.w], 1);
    }
}
__global__ void k_scan_a() {
    __shared__ int s[256];
    int tid = threadIdx.x;
    int i = blockIdx.x * 256 + tid;
    int v = (i < NN) ? g_cnt[i] : 0;
    s[tid] = v;
    __syncthreads();
    for (int d = 1; d < 256; d <<= 1) {
        int tv = 0;
        if (tid >= d) tv = s[tid - d];
        __syncthreads();
        if (tid >= d) s[tid] += tv;
        __syncthreads();
    }
    if (i < NN) g_off[i] = s[tid] - v;  // exclusive, block-local
    if (tid == 255) g_bsum[blockIdx.x] = s[255];
}
__global__ void k_scan_c() {
    __shared__ int red[256];
    int tid = threadIdx.x, bid = blockIdx.x;
    red[tid] = (tid < bid && tid < NB) ? g_bsum[tid] : 0;
    __syncthreads();
    for (int d = 128; d > 0; d >>= 1) {
        if (tid < d) red[tid] += red[tid + d];
        __syncthreads();
    }
    int base = red[0];
    int i = bid * 256 + tid;
    if (i < NN) {
        int o = g_off[i] + base;
        g_off[i] = o;
        g_cur[i] = o;
        g_dis[i] = rsqrtf((float)(g_cnt[i] + 1));  // +1 self loop
    }
    if (i == 0) g_off[NN] = NE;
}
__global__ void k_bucket(const int4* __restrict__ src4, const int4* __restrict__ dst4) {
    int i = blockIdx.x * blockDim.x + threadIdx.x;
    if (i < NE / 4) {
        int4 s = src4[i];
        int4 d = dst4[i];
        int p;
        p = atomicAdd(&g_cur[d.x], 1); g_csrc[p] = s.x;
        p = atomicAdd(&g_cur[d.y], 1); g_csrc[p] = s.y;
        p = atomicAdd(&g_cur[d.z], 1); g_csrc[p] = s.z;
        p = atomicAdd(&g_cur[d.w], 1); g_csrc[p] = s.w;
    }
    if (i < NN / 4) ((int4*)g_cnt)[i] = make_int4(0, 0, 0, 0);
}

// ================= bf16-split GEMM on mma.sync (HMMA, sm_80+ ISA) =================
// out[128 rows/CTA] = in(f32) @ W(f32) (+bias):
//   in = hi + lo (bf16 each); out ≈ hi@Whi + hi@Wlo + lo@Whi, fp32 accumulate.
// SMEM: A_hi/A_lo [128][TS], Bt_hi/Bt_lo [128][TS] with Bt[n][k] = W[k][n].
// TS=136 bf16 (68-word row stride) -> all fragment LDS are bank-conflict-free.

#define TS 136
#define TILE_ELEMS (128 * TS)
#define TG_SMEM (4 * TILE_ELEMS * 2)   // 139264 bytes

__device__ __forceinline__ void mma_bf16(float* d, unsigned a0, unsigned a1,
                                         unsigned a2, unsigned a3,
                                         unsigned b0, unsigned b1) {
    asm volatile(
        "mma.sync.aligned.m16n8k16.row.col.f32.bf16.bf16.f32 "
        "{%0,%1,%2,%3}, {%4,%5,%6,%7}, {%8,%9}, {%0,%1,%2,%3};"
        : "+f"(d[0]), "+f"(d[1]), "+f"(d[2]), "+f"(d[3])
        : "r"(a0), "r"(a1), "r"(a2), "r"(a3), "r"(b0), "r"(b1));
}
__device__ __forceinline__ unsigned ldb2(const __nv_bfloat16* p) {
    return *(const unsigned*)p;
}

__global__ __launch_bounds__(256, 1) void k_tgemm(const float* __restrict__ in,
                                                  const float* __restrict__ W,
                                                  const float* __restrict__ bias,
                                                  float* __restrict__ out) {
    extern __shared__ __nv_bfloat16 ts[];
    __nv_bfloat16* AH = ts;
    __nv_bfloat16* AL = AH + TILE_ELEMS;
    __nv_bfloat16* BH = AL + TILE_ELEMS;
    __nv_bfloat16* BL = BH + TILE_ELEMS;

    int tid = threadIdx.x;
    int row0 = blockIdx.x * 128;

    // ---- A: coalesced float2 reads, hi/lo split, conflict-free STS ----
    for (int e = tid; e < 8192; e += 256) {        // r = e>>6, c = 2*(e&63)
        int r = e >> 6, c = (e & 63) << 1;
        int gr = row0 + r;
        float2 v = (gr < NN) ? *(const float2*)&in[gr * C + c] : make_float2(0.f, 0.f);
        __nv_bfloat162 h = __floats2bfloat162_rn(v.x, v.y);
        float2 hf = __bfloat1622float2(h);
        __nv_bfloat162 l = __floats2bfloat162_rn(v.x - hf.x, v.y - hf.y);
        *(__nv_bfloat162*)&AH[r * TS + c] = h;
        *(__nv_bfloat162*)&AL[r * TS + c] = l;
    }
    // ---- Bt[n][k] = W[k][n]: coalesced reads of two W rows, transposed store ----
    for (int e = tid; e < 8192; e += 256) {        // n = e&127, k = 2*(e>>7)
        int n = e & 127, k = (e >> 7) << 1;
        float w0 = W[k * C + n], w1 = W[(k + 1) * C + n];
        __nv_bfloat162 h = __floats2bfloat162_rn(w0, w1);
        float2 hf = __bfloat1622float2(h);
        __nv_bfloat162 l = __floats2bfloat162_rn(w0 - hf.x, w1 - hf.y);
        *(__nv_bfloat162*)&BH[n * TS + k] = h;
        *(__nv_bfloat162*)&BL[n * TS + k] = l;
    }
    __syncthreads();

    int wid = tid >> 5, lane = tid & 31;
    int r0 = wid * 16;              // warp's 16 rows
    int lrow = lane >> 2;           // 0..7
    int lk = (lane & 3) << 1;       // 0,2,4,6

    float acc[16][4];
#pragma unroll
    for (int nt = 0; nt < 16; nt++)
#pragma unroll
        for (int j = 0; j < 4; j++) acc[nt][j] = 0.f;

#pragma unroll 1
    for (int kc = 0; kc < 8; kc++) {
        int kb = kc * 16 + lk;
        const __nv_bfloat16* ArH = AH + (r0 + lrow) * TS + kb;
        const __nv_bfloat16* ArL = AL + (r0 + lrow) * TS + kb;
        unsigned aH0 = ldb2(ArH),           aH1 = ldb2(ArH + 8 * TS);
        unsigned aH2 = ldb2(ArH + 8),       aH3 = ldb2(ArH + 8 * TS + 8);
        unsigned aL0 = ldb2(ArL),           aL1 = ldb2(ArL + 8 * TS);
        unsigned aL2 = ldb2(ArL + 8),       aL3 = ldb2(ArL + 8 * TS + 8);
#pragma unroll
        for (int nt = 0; nt < 16; nt++) {
            const __nv_bfloat16* BrH = BH + (nt * 8 + lrow) * TS + kb;
            const __nv_bfloat16* BrL = BL + (nt * 8 + lrow) * TS + kb;
            unsigned bH0 = ldb2(BrH), bH1 = ldb2(BrH + 8);
            unsigned bL0 = ldb2(BrL), bL1 = ldb2(BrL + 8);
            mma_bf16(acc[nt], aH0, aH1, aH2, aH3, bH0, bH1);
            mma_bf16(acc[nt], aH0, aH1, aH2, aH3, bL0, bL1);
            mma_bf16(acc[nt], aL0, aL1, aL2, aL3, bH0, bH1);
        }
    }

    // ---- epilogue: d0,d1 -> (r, c..c+1); d2,d3 -> (r+8, c..c+1) ----
    int gr0 = row0 + r0 + lrow;
    int gr1 = gr0 + 8;
#pragma unroll
    for (int nt = 0; nt < 16; nt++) {
        int col = nt * 8 + lk;
        float bx = 0.f, by = 0.f;
        if (bias) { bx = bias[col]; by = bias[col + 1]; }
        if (gr0 < NN)
            *(float2*)&out[gr0 * C + col] = make_float2(acc[nt][0] + bx, acc[nt][1] + by);
        if (gr1 < NN)
            *(float2*)&out[gr1 * C + col] = make_float2(acc[nt][2] + bx, acc[nt][3] + by);
    }
}

// ---------------- CSR gather: one warp per node, edge loop unrolled x4 ----------------
__global__ __launch_bounds__(256) void k_gather(const float* __restrict__ t,
                                                const float* __restrict__ b,
                                                const float* __restrict__ a,
                                                float* __restrict__ skip_io,
                                                float* __restrict__ out, int mode) {
    int node = (blockIdx.x * 256 + threadIdx.x) >> 5;
    int lane = threadIdx.x & 31;
    if (node >= NN) return;

    float di = g_dis[node];
    float d2 = di * di;
    float4 bv = ((const float4*)b)[lane];
    float4 tv = ((const float4*)t)[node * 32 + lane];
    float4 acc = make_float4(bv.x + tv.x * d2, bv.y + tv.y * d2,
                             bv.z + tv.z * d2, bv.w + tv.w * d2);

    int beg = g_off[node], end = g_off[node + 1];
    for (int base = beg; base < end; base += 32) {
        int idx = base + lane;
        int s = 0;
        float w = 0.f;
        if (idx < end) {
            s = g_csrc[idx];
            w = g_dis[s] * di;
        }
        int cnt = min(32, end - base);
        int j = 0;
        for (; j + 4 <= cnt; j += 4) {
            int s0 = __shfl_sync(0xffffffffu, s, j);
            int s1 = __shfl_sync(0xffffffffu, s, j + 1);
            int s2 = __shfl_sync(0xffffffffu, s, j + 2);
            int s3 = __shfl_sync(0xffffffffu, s, j + 3);
            float w0 = __shfl_sync(0xffffffffu, w, j);
            float w1 = __shfl_sync(0xffffffffu, w, j + 1);
            float w2 = __shfl_sync(0xffffffffu, w, j + 2);
            float w3 = __shfl_sync(0xffffffffu, w, j + 3);
            float4 v0 = ((const float4*)t)[s0 * 32 + lane];
            float4 v1 = ((const float4*)t)[s1 * 32 + lane];
            float4 v2 = ((const float4*)t)[s2 * 32 + lane];
            float4 v3 = ((const float4*)t)[s3 * 32 + lane];
            acc.x += v0.x * w0; acc.y += v0.y * w0; acc.z += v0.z * w0; acc.w += v0.w * w0;
            acc.x += v1.x * w1; acc.y += v1.y * w1; acc.z += v1.z * w1; acc.w += v1.w * w1;
            acc.x += v2.x * w2; acc.y += v2.y * w2; acc.z += v2.z * w2; acc.w += v2.w * w2;
            acc.x += v3.x * w3; acc.y += v3.y * w3; acc.z += v3.z * w3; acc.w += v3.w * w3;
        }
        for (; j < cnt; j++) {
            int sj = __shfl_sync(0xffffffffu, s, j);
            float wj = __shfl_sync(0xffffffffu, w, j);
            float4 v = ((const float4*)t)[sj * 32 + lane];
            acc.x += v.x * wj; acc.y += v.y * wj; acc.z += v.z * wj; acc.w += v.w * wj;
        }
    }

    float4 av = ((const float4*)a)[lane];
    float4 p;
    p.x = acc.x >= 0.f ? acc.x : av.x * acc.x;
    p.y = acc.y >= 0.f ? acc.y : av.y * acc.y;
    p.z = acc.z >= 0.f ? acc.z : av.z * acc.z;
    p.w = acc.w >= 0.f ? acc.w : av.w * acc.w;

    if (mode == 0) {
        float4 sk = ((const float4*)skip_io)[node * 32 + lane];
        ((float4*)skip_io)[node * 32 + lane] =
            make_float4(sk.x + p.x, sk.y + p.y, sk.z + p.z, sk.w + p.w);
    } else {
        ((float4*)out)[node * 32 + lane] = p;
    }
}

extern "C" void kernel_launch(void* const* d_in, const int* in_sizes, int n_in,
                              void* d_out, int out_size) {
    const float* x  = (const float*)d_in[0];
    const int*   ei = (const int*)d_in[1];
    const float* W0 = (const float*)d_in[2];
    const float* b0 = (const float*)d_in[3];
    const float* W1 = (const float*)d_in[4];
    const float* b1 = (const float*)d_in[5];
    const float* Ws = (const float*)d_in[6];
    const float* bs = (const float*)d_in[7];
    const float* a  = (const float*)d_in[8];
    float* out = (float*)d_out;

    const int4* src4 = (const int4*)ei;
    const int4* dst4 = (const int4*)(ei + NE);

    float *t, *skip;
    cudaGetSymbolAddress((void**)&t, g_t);
    cudaGetSymbolAddress((void**)&skip, g_skip);

    cudaFuncSetAttribute(k_tgemm, cudaFuncAttributeMaxDynamicSharedMemorySize, TG_SMEM);

    const int TG_GRID = (NN + 127) / 128;  // 391
    const int GATHER_GRID = (NN * 32 + 255) / 256;
    const int E4 = NE / 4;

    // 9 launches; index 3 (ncu capture slot) = first tensor GEMM
    k_deg_count<<<(E4 + 255) / 256, 256>>>(dst4);                 // 0
    k_scan_a<<<NB, 256>>>();                                      // 1
    k_scan_c<<<NB, 256>>>();                                      // 2

    k_tgemm<<<TG_GRID, 256, TG_SMEM>>>(x, Ws, bs, skip);          // 3: skip = x@Ws+bs [ncu]
    k_tgemm<<<TG_GRID, 256, TG_SMEM>>>(x, W0, nullptr, t);        // 4: t = x@W0

    k_bucket<<<(E4 + 255) / 256, 256>>>(src4, dst4);              // 5 (re-zeros g_cnt)
    k_gather<<<GATHER_GRID, 256>>>(t, b0, a, skip, nullptr, 0);   // 6: skip = u

    k_tgemm<<<TG_GRID, 256, TG_SMEM>>>(skip, W1, nullptr, t);     // 7: t = u@W1
    k_gather<<<GATHER_GRID, 256>>>(t, b1, a, nullptr, out, 1);    // 8: out
}

// round 14
// speedup vs baseline: 1.4088x; 1.1360x over previous
#include <cuda_runtime.h>
#include <cuda_bf16.h>

#define NN 50000
#define NE 600000
#define C  128
#define NB ((NN + 255) / 256)   // 196 scan blocks

// ---------------- scratch (static __device__, zero-initialized at load) ----------------
__device__ int   g_cnt[NN];      // stays zero between pipeline runs (bucket re-zeros)
__device__ int   g_off[NN + 1];
__device__ int   g_cur[NN];
__device__ int   g_bsum[NB];
__device__ int   g_csrc[NE];
__device__ float g_dis[NN];
__device__ float g_t[NN * C];
__device__ float g_skip[NN * C];

// ---------------- CSR build ----------------
__global__ void k_deg_count(const int4* __restrict__ dst4) {
    int i = blockIdx.x * blockDim.x + threadIdx.x;
    if (i < NE / 4) {
        int4 d = dst4[i];
        atomicAdd(&g_cnt[d.x], 1);
        atomicAdd(&g_cnt[d.y], 1);
        atomicAdd(&g_cnt[d.z], 1);
        atomicAdd(&g_cnt[d.w], 1);
    }
}
__global__ void k_scan_a() {
    __shared__ int s[256];
    int tid = threadIdx.x;
    int i = blockIdx.x * 256 + tid;
    int v = (i < NN) ? g_cnt[i] : 0;
    s[tid] = v;
    __syncthreads();
    for (int d = 1; d < 256; d <<= 1) {
        int tv = 0;
        if (tid >= d) tv = s[tid - d];
        __syncthreads();
        if (tid >= d) s[tid] += tv;
        __syncthreads();
    }
    if (i < NN) g_off[i] = s[tid] - v;  // exclusive, block-local
    if (tid == 255) g_bsum[blockIdx.x] = s[255];
}
__global__ void k_scan_c() {
    __shared__ int red[256];
    int tid = threadIdx.x, bid = blockIdx.x;
    red[tid] = (tid < bid && tid < NB) ? g_bsum[tid] : 0;
    __syncthreads();
    for (int d = 128; d > 0; d >>= 1) {
        if (tid < d) red[tid] += red[tid + d];
        __syncthreads();
    }
    int base = red[0];
    int i = bid * 256 + tid;
    if (i < NN) {
        int o = g_off[i] + base;
        g_off[i] = o;
        g_cur[i] = o;
        g_dis[i] = rsqrtf((float)(g_cnt[i] + 1));  // +1 self loop
    }
    if (i == 0) g_off[NN] = NE;
}
__global__ void k_bucket(const int4* __restrict__ src4, const int4* __restrict__ dst4) {
    int i = blockIdx.x * blockDim.x + threadIdx.x;
    if (i < NE / 4) {
        int4 s = src4[i];
        int4 d = dst4[i];
        int p;
        p = atomicAdd(&g_cur[d.x], 1); g_csrc[p] = s.x;
        p = atomicAdd(&g_cur[d.y], 1); g_csrc[p] = s.y;
        p = atomicAdd(&g_cur[d.z], 1); g_csrc[p] = s.z;
        p = atomicAdd(&g_cur[d.w], 1); g_csrc[p] = s.w;
    }
    if (i < NN / 4) ((int4*)g_cnt)[i] = make_int4(0, 0, 0, 0);
}

// ================= bf16-split GEMM on mma.sync + ldmatrix =================
// out[128 rows/CTA] = in(f32) @ W(f32) (+bias):
//   in = hi + lo (bf16 each); out ≈ hi@Whi + hi@Wlo + lo@Whi, fp32 accumulate.
// K staged in two 64-wide halves -> 72KB smem -> 2 CTAs/SM.
// Warp tile 32r x 64c (warps: 4 m-groups x 2 n-groups). ldmatrix.x4 fragments.

#define TSS 72                      // bf16 elems per staged row (64 + 8 pad)
#define STAGE_ELEMS (128 * TSS)
#define TG_SMEM (4 * STAGE_ELEMS * 2)   // 73728 bytes

__device__ __forceinline__ unsigned s2u(const void* p) {
    unsigned a;
    asm("{ .reg .u64 t; cvta.to.shared.u64 t, %1; cvt.u32.u64 %0, t; }" : "=r"(a) : "l"(p));
    return a;
}
__device__ __forceinline__ void mma_bf16(float* d, const unsigned* a,
                                         unsigned b0, unsigned b1) {
    asm volatile(
        "mma.sync.aligned.m16n8k16.row.col.f32.bf16.bf16.f32 "
        "{%0,%1,%2,%3}, {%4,%5,%6,%7}, {%8,%9}, {%0,%1,%2,%3};"
        : "+f"(d[0]), "+f"(d[1]), "+f"(d[2]), "+f"(d[3])
        : "r"(a[0]), "r"(a[1]), "r"(a[2]), "r"(a[3]), "r"(b0), "r"(b1));
}
__device__ __forceinline__ void ldm4(unsigned* r, unsigned addr) {
    asm volatile("ldmatrix.sync.aligned.m8n8.x4.shared.b16 {%0,%1,%2,%3}, [%4];"
                 : "=r"(r[0]), "=r"(r[1]), "=r"(r[2]), "=r"(r[3]) : "r"(addr));
}

__global__ __launch_bounds__(256, 2) void k_tgemm(const float* __restrict__ in,
                                                  const float* __restrict__ W,
                                                  const float* __restrict__ bias,
                                                  float* __restrict__ out) {
    extern __shared__ __nv_bfloat16 ts[];
    __nv_bfloat16* AH = ts;
    __nv_bfloat16* AL = AH + STAGE_ELEMS;
    __nv_bfloat16* BH = AL + STAGE_ELEMS;
    __nv_bfloat16* BL = BH + STAGE_ELEMS;

    int tid = threadIdx.x;
    int row0 = blockIdx.x * 128;
    int wid = tid >> 5, lane = tid & 31;
    int r0 = (wid & 3) * 32;        // warp m-group: rows r0..r0+31
    int c0 = (wid >> 2) * 64;       // warp n-group: cols c0..c0+63
    int lrow = lane >> 2;           // 0..7
    int lk = (lane & 3) << 1;       // 0,2,4,6
    int mi = lane >> 3, rr = lane & 7;
    // ldmatrix per-thread element offsets (A: a0=(r,k) a1=(r+8,k) a2=(r,k+8) a3=(r+8,k+8);
    //                                      B: b0t0=(n,k) b1t0=(n,k+8) b0t1=(n+8,k) b1t1=(n+8,k+8))
    int aoff = ((mi & 1) * 8 + rr) * TSS + (mi >> 1) * 8;
    int boff = ((mi >> 1) * 8 + rr) * TSS + (mi & 1) * 8;
    unsigned AHu = s2u(AH), ALu = s2u(AL), BHu = s2u(BH), BLu = s2u(BL);

    float acc[2][8][4];
#pragma unroll
    for (int m = 0; m < 2; m++)
#pragma unroll
        for (int nt = 0; nt < 8; nt++)
#pragma unroll
            for (int j = 0; j < 4; j++) acc[m][nt][j] = 0.f;

#pragma unroll 1
    for (int ks = 0; ks < 2; ks++) {
        int k0 = ks * 64;
        if (ks) __syncthreads();  // prior compute done before overwrite
        // ---- stage A: coalesced float2 reads, hi/lo split ----
        for (int e = tid; e < 4096; e += 256) {   // r = e>>5, c = 2*(e&31)
            int r = e >> 5, c = (e & 31) << 1;
            int gr = row0 + r;
            float2 v = (gr < NN) ? *(const float2*)&in[gr * C + k0 + c]
                                 : make_float2(0.f, 0.f);
            __nv_bfloat162 h = __floats2bfloat162_rn(v.x, v.y);
            float2 hf = __bfloat1622float2(h);
            __nv_bfloat162 l = __floats2bfloat162_rn(v.x - hf.x, v.y - hf.y);
            *(__nv_bfloat162*)&AH[r * TSS + c] = h;
            *(__nv_bfloat162*)&AL[r * TSS + c] = l;
        }
        // ---- stage Bt[n][k] = W[k0+k][n]: coalesced reads over n ----
        for (int e = tid; e < 4096; e += 256) {   // n = e&127, kk = 2*(e>>7)
            int n = e & 127, kk = (e >> 7) << 1;
            float w0 = W[(k0 + kk) * C + n], w1 = W[(k0 + kk + 1) * C + n];
            __nv_bfloat162 h = __floats2bfloat162_rn(w0, w1);
            float2 hf = __bfloat1622float2(h);
            __nv_bfloat162 l = __floats2bfloat162_rn(w0 - hf.x, w1 - hf.y);
            *(__nv_bfloat162*)&BH[n * TSS + kk] = h;
            *(__nv_bfloat162*)&BL[n * TSS + kk] = l;
        }
        __syncthreads();

#pragma unroll
        for (int kc = 0; kc < 4; kc++) {
            int kb = kc * 16;
            unsigned a0o = 2u * (unsigned)(r0 * TSS + kb + aoff);
            unsigned a1o = 2u * (unsigned)((r0 + 16) * TSS + kb + aoff);
            unsigned aH0[4], aH1[4], aL0[4], aL1[4];
            ldm4(aH0, AHu + a0o);
            ldm4(aH1, AHu + a1o);
            ldm4(aL0, ALu + a0o);
            ldm4(aL1, ALu + a1o);
#pragma unroll
            for (int np = 0; np < 4; np++) {
                unsigned bo = 2u * (unsigned)((c0 + np * 16) * TSS + kb + boff);
                unsigned bh[4], bl[4];
                ldm4(bh, BHu + bo);
                ldm4(bl, BLu + bo);
                int nt0 = np * 2, nt1 = np * 2 + 1;
                mma_bf16(acc[0][nt0], aH0, bh[0], bh[1]);
                mma_bf16(acc[0][nt0], aH0, bl[0], bl[1]);
                mma_bf16(acc[0][nt0], aL0, bh[0], bh[1]);
                mma_bf16(acc[0][nt1], aH0, bh[2], bh[3]);
                mma_bf16(acc[0][nt1], aH0, bl[2], bl[3]);
                mma_bf16(acc[0][nt1], aL0, bh[2], bh[3]);
                mma_bf16(acc[1][nt0], aH1, bh[0], bh[1]);
                mma_bf16(acc[1][nt0], aH1, bl[0], bl[1]);
                mma_bf16(acc[1][nt0], aL1, bh[0], bh[1]);
                mma_bf16(acc[1][nt1], aH1, bh[2], bh[3]);
                mma_bf16(acc[1][nt1], aH1, bl[2], bl[3]);
                mma_bf16(acc[1][nt1], aL1, bh[2], bh[3]);
            }
        }
    }

    // ---- epilogue: d0,d1 -> (r, col..col+1); d2,d3 -> (r+8, ...) ----
#pragma unroll
    for (int m = 0; m < 2; m++) {
        int gr0 = row0 + r0 + m * 16 + lrow;
        int gr1 = gr0 + 8;
#pragma unroll
        for (int nt = 0; nt < 8; nt++) {
            int col = c0 + nt * 8 + lk;
            float bx = 0.f, by = 0.f;
            if (bias) { bx = bias[col]; by = bias[col + 1]; }
            if (gr0 < NN)
                *(float2*)&out[gr0 * C + col] =
                    make_float2(acc[m][nt][0] + bx, acc[m][nt][1] + by);
            if (gr1 < NN)
                *(float2*)&out[gr1 * C + col] =
                    make_float2(acc[m][nt][2] + bx, acc[m][nt][3] + by);
        }
    }
}

// ---------------- CSR gather: one warp per node, edge loop unrolled x4 ----------------
__global__ __launch_bounds__(256) void k_gather(const float* __restrict__ t,
                                                const float* __restrict__ b,
                                                const float* __restrict__ a,
                                                float* __restrict__ skip_io,
                                                float* __restrict__ out, int mode) {
    int node = (blockIdx.x * 256 + threadIdx.x) >> 5;
    int lane = threadIdx.x & 31;
    if (node >= NN) return;

    float di = g_dis[node];
    float d2 = di * di;
    float4 bv = ((const float4*)b)[lane];
    float4 tv = ((const float4*)t)[node * 32 + lane];
    float4 acc = make_float4(bv.x + tv.x * d2, bv.y + tv.y * d2,
                             bv.z + tv.z * d2, bv.w + tv.w * d2);

    int beg = g_off[node], end = g_off[node + 1];
    for (int base = beg; base < end; base += 32) {
        int idx = base + lane;
        int s = 0;
        float w = 0.f;
        if (idx < end) {
            s = g_csrc[idx];
            w = g_dis[s] * di;
        }
        int cnt = min(32, end - base);
        int j = 0;
        for (; j + 4 <= cnt; j += 4) {
            int s0 = __shfl_sync(0xffffffffu, s, j);
            int s1 = __shfl_sync(0xffffffffu, s, j + 1);
            int s2 = __shfl_sync(0xffffffffu, s, j + 2);
            int s3 = __shfl_sync(0xffffffffu, s, j + 3);
            float w0 = __shfl_sync(0xffffffffu, w, j);
            float w1 = __shfl_sync(0xffffffffu, w, j + 1);
            float w2 = __shfl_sync(0xffffffffu, w, j + 2);
            float w3 = __shfl_sync(0xffffffffu, w, j + 3);
            float4 v0 = ((const float4*)t)[s0 * 32 + lane];
            float4 v1 = ((const float4*)t)[s1 * 32 + lane];
            float4 v2 = ((const float4*)t)[s2 * 32 + lane];
            float4 v3 = ((const float4*)t)[s3 * 32 + lane];
            acc.x += v0.x * w0; acc.y += v0.y * w0; acc.z += v0.z * w0; acc.w += v0.w * w0;
            acc.x += v1.x * w1; acc.y += v1.y * w1; acc.z += v1.z * w1; acc.w += v1.w * w1;
            acc.x += v2.x * w2; acc.y += v2.y * w2; acc.z += v2.z * w2; acc.w += v2.w * w2;
            acc.x += v3.x * w3; acc.y += v3.y * w3; acc.z += v3.z * w3; acc.w += v3.w * w3;
        }
        for (; j < cnt; j++) {
            int sj = __shfl_sync(0xffffffffu, s, j);
            float wj = __shfl_sync(0xffffffffu, w, j);
            float4 v = ((const float4*)t)[sj * 32 + lane];
            acc.x += v.x * wj; acc.y += v.y * wj; acc.z += v.z * wj; acc.w += v.w * wj;
        }
    }

    float4 av = ((const float4*)a)[lane];
    float4 p;
    p.x = acc.x >= 0.f ? acc.x : av.x * acc.x;
    p.y = acc.y >= 0.f ? acc.y : av.y * acc.y;
    p.z = acc.z >= 0.f ? acc.z : av.z * acc.z;
    p.w = acc.w >= 0.f ? acc.w : av.w * acc.w;

    if (mode == 0) {
        float4 sk = ((const float4*)skip_io)[node * 32 + lane];
        ((float4*)skip_io)[node * 32 + lane] =
            make_float4(sk.x + p.x, sk.y + p.y, sk.z + p.z, sk.w + p.w);
    } else {
        ((float4*)out)[node * 32 + lane] = p;
    }
}

extern "C" void kernel_launch(void* const* d_in, const int* in_sizes, int n_in,
                              void* d_out, int out_size) {
    const float* x  = (const float*)d_in[0];
    const int*   ei = (const int*)d_in[1];
    const float* W0 = (const float*)d_in[2];
    const float* b0 = (const float*)d_in[3];
    const float* W1 = (const float*)d_in[4];
    const float* b1 = (const float*)d_in[5];
    const float* Ws = (const float*)d_in[6];
    const float* bs = (const float*)d_in[7];
    const float* a  = (const float*)d_in[8];
    float* out = (float*)d_out;

    const int4* src4 = (const int4*)ei;
    const int4* dst4 = (const int4*)(ei + NE);

    float *t, *skip;
    cudaGetSymbolAddress((void**)&t, g_t);
    cudaGetSymbolAddress((void**)&skip, g_skip);

    cudaFuncSetAttribute(k_tgemm, cudaFuncAttributeMaxDynamicSharedMemorySize, TG_SMEM);

    const int TG_GRID = (NN + 127) / 128;  // 391
    const int GATHER_GRID = (NN * 32 + 255) / 256;
    const int E4 = NE / 4;

    // 9 launches; index 3 (ncu capture slot) = first tensor GEMM
    k_deg_count<<<(E4 + 255) / 256, 256>>>(dst4);                 // 0
    k_scan_a<<<NB, 256>>>();                                      // 1
    k_scan_c<<<NB, 256>>>();                                      // 2

    k_tgemm<<<TG_GRID, 256, TG_SMEM>>>(x, Ws, bs, skip);          // 3: skip = x@Ws+bs [ncu]
    k_tgemm<<<TG_GRID, 256, TG_SMEM>>>(x, W0, nullptr, t);        // 4: t = x@W0

    k_bucket<<<(E4 + 255) / 256, 256>>>(src4, dst4);              // 5 (re-zeros g_cnt)
    k_gather<<<GATHER_GRID, 256>>>(t, b0, a, skip, nullptr, 0);   // 6: skip = u

    k_tgemm<<<TG_GRID, 256, TG_SMEM>>>(skip, W1, nullptr, t);     // 7: t = u@W1
    k_gather<<<GATHER_GRID, 256>>>(t, b1, a, nullptr, out, 1);    // 8: out
}

// round 16
// speedup vs baseline: 1.5124x; 1.0736x over previous
#include <cuda_runtime.h>
#include <cuda_bf16.h>

#define NN 50000
#define NE 600000
#define C  128
#define NB ((NN + 255) / 256)   // 196 scan blocks

// ---------------- scratch (static __device__, zero-initialized at load) ----------------
__device__ int   g_cnt[NN];      // stays zero between pipeline runs (bucket re-zeros)
__device__ int   g_off[NN + 1];
__device__ int   g_cur[NN];
__device__ int   g_bsum[NB];
__device__ int   g_csrc[NE];
__device__ float g_dis[NN];
__device__ float g_t[NN * C];
__device__ float g_skip[NN * C];
__device__ __nv_bfloat16 g_bth[3 * C * C];  // [mat][n][k] = hi(W[k][n])
__device__ __nv_bfloat16 g_btl[3 * C * C];  // [mat][n][k] = lo(W[k][n])

// ---------------- CSR build ----------------
__global__ void k_deg_count(const int4* __restrict__ dst4) {
    int i = blockIdx.x * blockDim.x + threadIdx.x;
    if (i < NE / 4) {
        int4 d = dst4[i];
        atomicAdd(&g_cnt[d.x], 1);
        atomicAdd(&g_cnt[d.y], 1);
        atomicAdd(&g_cnt[d.z], 1);
        atomicAdd(&g_cnt[d.w], 1);
    }
}
__global__ void k_scan_a() {
    __shared__ int s[256];
    int tid = threadIdx.x;
    int i = blockIdx.x * 256 + tid;
    int v = (i < NN) ? g_cnt[i] : 0;
    s[tid] = v;
    __syncthreads();
    for (int d = 1; d < 256; d <<= 1) {
        int tv = 0;
        if (tid >= d) tv = s[tid - d];
        __syncthreads();
        if (tid >= d) s[tid] += tv;
        __syncthreads();
    }
    if (i < NN) g_off[i] = s[tid] - v;  // exclusive, block-local
    if (tid == 255) g_bsum[blockIdx.x] = s[255];
}
__global__ void k_scan_c() {
    __shared__ int red[256];
    int tid = threadIdx.x, bid = blockIdx.x;
    red[tid] = (tid < bid && tid < NB) ? g_bsum[tid] : 0;
    __syncthreads();
    for (int d = 128; d > 0; d >>= 1) {
        if (tid < d) red[tid] += red[tid + d];
        __syncthreads();
    }
    int base = red[0];
    int i = bid * 256 + tid;
    if (i < NN) {
        int o = g_off[i] + base;
        g_off[i] = o;
        g_cur[i] = o;
        g_dis[i] = rsqrtf((float)(g_cnt[i] + 1));  // +1 self loop
    }
    if (i == 0) g_off[NN] = NE;
}
__global__ void k_bucket(const int4* __restrict__ src4, const int4* __restrict__ dst4) {
    int i = blockIdx.x * blockDim.x + threadIdx.x;
    if (i < NE / 4) {
        int4 s = src4[i];
        int4 d = dst4[i];
        int p;
        p = atomicAdd(&g_cur[d.x], 1); g_csrc[p] = s.x;
        p = atomicAdd(&g_cur[d.y], 1); g_csrc[p] = s.y;
        p = atomicAdd(&g_cur[d.z], 1); g_csrc[p] = s.z;
        p = atomicAdd(&g_cur[d.w], 1); g_csrc[p] = s.w;
    }
    if (i < NN / 4) ((int4*)g_cnt)[i] = make_int4(0, 0, 0, 0);
}

// ---------------- W split/transpose precompute: mats {0:W0, 1:W1, 2:Ws} ----------------
__global__ void k_wsplit(const float* __restrict__ W0, const float* __restrict__ W1,
                         const float* __restrict__ Ws) {
    int i = blockIdx.x * blockDim.x + threadIdx.x;
    if (i >= 3 * C * C) return;
    int mat = i >> 14, e = i & (C * C - 1);
    int n = e & 127, k = e >> 7;
    const float* W = (mat == 0) ? W0 : (mat == 1) ? W1 : Ws;
    float w = W[k * C + n];
    __nv_bfloat16 h = __float2bfloat16(w);
    __nv_bfloat16 l = __float2bfloat16(w - __bfloat162float(h));
    int dst = mat * C * C + n * C + k;
    g_bth[dst] = h;
    g_btl[dst] = l;
}

// ================= bf16-split GEMM on mma.sync + ldmatrix =================
// out[128 rows/CTA] = in(f32) @ W(f32) (+bias), W pre-split/transposed in g_bt*.
// A (hi/lo) resident full-K in smem (TS=136 rows); B staged in two K=64 halves
// (TSS=72 rows) as pure bf16 copies. 104KB smem -> 2 CTAs/SM.
// Warp tile 32r x 64c (4 m-groups x 2 n-groups), ldmatrix.x4 fragments.

#define TS  136
#define TSS 72
#define A_ELEMS (128 * TS)
#define B_ELEMS (128 * TSS)
#define TG_SMEM ((2 * A_ELEMS + 2 * B_ELEMS) * 2)   // 106496 bytes

__device__ __forceinline__ unsigned s2u(const void* p) {
    unsigned a;
    asm("{ .reg .u64 t; cvta.to.shared.u64 t, %1; cvt.u32.u64 %0, t; }" : "=r"(a) : "l"(p));
    return a;
}
__device__ __forceinline__ void mma_bf16(float* d, const unsigned* a,
                                         unsigned b0, unsigned b1) {
    asm volatile(
        "mma.sync.aligned.m16n8k16.row.col.f32.bf16.bf16.f32 "
        "{%0,%1,%2,%3}, {%4,%5,%6,%7}, {%8,%9}, {%0,%1,%2,%3};"
        : "+f"(d[0]), "+f"(d[1]), "+f"(d[2]), "+f"(d[3])
        : "r"(a[0]), "r"(a[1]), "r"(a[2]), "r"(a[3]), "r"(b0), "r"(b1));
}
__device__ __forceinline__ void ldm4(unsigned* r, unsigned addr) {
    asm volatile("ldmatrix.sync.aligned.m8n8.x4.shared.b16 {%0,%1,%2,%3}, [%4];"
                 : "=r"(r[0]), "=r"(r[1]), "=r"(r[2]), "=r"(r[3]) : "r"(addr));
}

__global__ __launch_bounds__(256, 2) void k_tgemm(const float* __restrict__ in,
                                                  const __nv_bfloat16* __restrict__ bth,
                                                  const __nv_bfloat16* __restrict__ btl,
                                                  const float* __restrict__ bias,
                                                  float* __restrict__ out) {
    extern __shared__ __nv_bfloat16 ts[];
    __nv_bfloat16* AH = ts;
    __nv_bfloat16* AL = AH + A_ELEMS;
    __nv_bfloat16* BH = AL + A_ELEMS;
    __nv_bfloat16* BL = BH + B_ELEMS;

    int tid = threadIdx.x;
    int row0 = blockIdx.x * 128;
    int wid = tid >> 5, lane = tid & 31;
    int r0 = (wid & 3) * 32;        // warp m-group: rows r0..r0+31
    int c0 = (wid >> 2) * 64;       // warp n-group: cols c0..c0+63
    int lrow = lane >> 2;           // 0..7
    int lk = (lane & 3) << 1;       // 0,2,4,6
    int mi = lane >> 3, rr = lane & 7;
    int aoff = ((mi & 1) * 8 + rr) * TS + (mi >> 1) * 8;
    int boff = ((mi >> 1) * 8 + rr) * TSS + (mi & 1) * 8;
    unsigned AHu = s2u(AH), ALu = s2u(AL), BHu = s2u(BH), BLu = s2u(BL);

    // ---- stage A once (full K): coalesced float2 reads, hi/lo split ----
    for (int e = tid; e < 8192; e += 256) {   // r = e>>6, c = 2*(e&63)
        int r = e >> 6, c = (e & 63) << 1;
        int gr = row0 + r;
        float2 v = (gr < NN) ? *(const float2*)&in[gr * C + c] : make_float2(0.f, 0.f);
        __nv_bfloat162 h = __floats2bfloat162_rn(v.x, v.y);
        float2 hf = __bfloat1622float2(h);
        __nv_bfloat162 l = __floats2bfloat162_rn(v.x - hf.x, v.y - hf.y);
        *(__nv_bfloat162*)&AH[r * TS + c] = h;
        *(__nv_bfloat162*)&AL[r * TS + c] = l;
    }

    float acc[2][8][4];
#pragma unroll
    for (int m = 0; m < 2; m++)
#pragma unroll
        for (int nt = 0; nt < 8; nt++)
#pragma unroll
            for (int j = 0; j < 4; j++) acc[m][nt][j] = 0.f;

#pragma unroll 1
    for (int ks = 0; ks < 2; ks++) {
        int k0 = ks * 64;
        if (ks) __syncthreads();  // prior compute done before overwrite
        // ---- stage B half: pure bf16 int4 copies from precomputed global ----
        for (int e = tid; e < 2048; e += 256) {
            int tile = e >> 10, rem = e & 1023;
            int n = rem >> 3, ch = (rem & 7) << 3;       // 8 bf16 per int4
            const __nv_bfloat16* src = (tile ? btl : bth) + n * C + k0 + ch;
            __nv_bfloat16* dst = (tile ? BL : BH) + n * TSS + ch;
            *(int4*)dst = *(const int4*)src;
        }
        __syncthreads();

#pragma unroll
        for (int kc = 0; kc < 4; kc++) {
            int kbA = k0 + kc * 16;   // A is full-K resident
            int kbB = kc * 16;        // B is per-stage
            unsigned a0o = 2u * (unsigned)(r0 * TS + kbA + aoff);
            unsigned a1o = 2u * (unsigned)((r0 + 16) * TS + kbA + aoff);
            unsigned aH0[4], aH1[4], aL0[4], aL1[4];
            ldm4(aH0, AHu + a0o);
            ldm4(aH1, AHu + a1o);
            ldm4(aL0, ALu + a0o);
            ldm4(aL1, ALu + a1o);
#pragma unroll
            for (int np = 0; np < 4; np++) {
                unsigned bo = 2u * (unsigned)((c0 + np * 16) * TSS + kbB + boff);
                unsigned bh[4], bl[4];
                ldm4(bh, BHu + bo);
                ldm4(bl, BLu + bo);
                int nt0 = np * 2, nt1 = np * 2 + 1;
                mma_bf16(acc[0][nt0], aH0, bh[0], bh[1]);
                mma_bf16(acc[0][nt0], aH0, bl[0], bl[1]);
                mma_bf16(acc[0][nt0], aL0, bh[0], bh[1]);
                mma_bf16(acc[0][nt1], aH0, bh[2], bh[3]);
                mma_bf16(acc[0][nt1], aH0, bl[2], bl[3]);
                mma_bf16(acc[0][nt1], aL0, bh[2], bh[3]);
                mma_bf16(acc[1][nt0], aH1, bh[0], bh[1]);
                mma_bf16(acc[1][nt0], aH1, bl[0], bl[1]);
                mma_bf16(acc[1][nt0], aL1, bh[0], bh[1]);
                mma_bf16(acc[1][nt1], aH1, bh[2], bh[3]);
                mma_bf16(acc[1][nt1], aH1, bl[2], bl[3]);
                mma_bf16(acc[1][nt1], aL1, bh[2], bh[3]);
            }
        }
    }

    // ---- epilogue: d0,d1 -> (r, col..col+1); d2,d3 -> (r+8, ...) ----
#pragma unroll
    for (int m = 0; m < 2; m++) {
        int gr0 = row0 + r0 + m * 16 + lrow;
        int gr1 = gr0 + 8;
#pragma unroll
        for (int nt = 0; nt < 8; nt++) {
            int col = c0 + nt * 8 + lk;
            float bx = 0.f, by = 0.f;
            if (bias) { bx = bias[col]; by = bias[col + 1]; }
            if (gr0 < NN)
                *(float2*)&out[gr0 * C + col] =
                    make_float2(acc[m][nt][0] + bx, acc[m][nt][1] + by);
            if (gr1 < NN)
                *(float2*)&out[gr1 * C + col] =
                    make_float2(acc[m][nt][2] + bx, acc[m][nt][3] + by);
        }
    }
}

// ---------------- CSR gather: one warp per node, edge loop unrolled x4 ----------------
__global__ __launch_bounds__(256) void k_gather(const float* __restrict__ t,
                                                const float* __restrict__ b,
                                                const float* __restrict__ a,
                                                float* __restrict__ skip_io,
                                                float* __restrict__ out, int mode) {
    int node = (blockIdx.x * 256 + threadIdx.x) >> 5;
    int lane = threadIdx.x & 31;
    if (node >= NN) return;

    float di = g_dis[node];
    float d2 = di * di;
    float4 bv = ((const float4*)b)[lane];
    float4 tv = ((const float4*)t)[node * 32 + lane];
    float4 acc = make_float4(bv.x + tv.x * d2, bv.y + tv.y * d2,
                             bv.z + tv.z * d2, bv.w + tv.w * d2);

    int beg = g_off[node], end = g_off[node + 1];
    for (int base = beg; base < end; base += 32) {
        int idx = base + lane;
        int s = 0;
        float w = 0.f;
        if (idx < end) {
            s = g_csrc[idx];
            w = g_dis[s] * di;
        }
        int cnt = min(32, end - base);
        int j = 0;
        for (; j + 4 <= cnt; j += 4) {
            int s0 = __shfl_sync(0xffffffffu, s, j);
            int s1 = __shfl_sync(0xffffffffu, s, j + 1);
            int s2 = __shfl_sync(0xffffffffu, s, j + 2);
            int s3 = __shfl_sync(0xffffffffu, s, j + 3);
            float w0 = __shfl_sync(0xffffffffu, w, j);
            float w1 = __shfl_sync(0xffffffffu, w, j + 1);
            float w2 = __shfl_sync(0xffffffffu, w, j + 2);
            float w3 = __shfl_sync(0xffffffffu, w, j + 3);
            float4 v0 = ((const float4*)t)[s0 * 32 + lane];
            float4 v1 = ((const float4*)t)[s1 * 32 + lane];
            float4 v2 = ((const float4*)t)[s2 * 32 + lane];
            float4 v3 = ((const float4*)t)[s3 * 32 + lane];
            acc.x += v0.x * w0; acc.y += v0.y * w0; acc.z += v0.z * w0; acc.w += v0.w * w0;
            acc.x += v1.x * w1; acc.y += v1.y * w1; acc.z += v1.z * w1; acc.w += v1.w * w1;
            acc.x += v2.x * w2; acc.y += v2.y * w2; acc.z += v2.z * w2; acc.w += v2.w * w2;
            acc.x += v3.x * w3; acc.y += v3.y * w3; acc.z += v3.z * w3; acc.w += v3.w * w3;
        }
        for (; j < cnt; j++) {
            int sj = __shfl_sync(0xffffffffu, s, j);
            float wj = __shfl_sync(0xffffffffu, w, j);
            float4 v = ((const float4*)t)[sj * 32 + lane];
            acc.x += v.x * wj; acc.y += v.y * wj; acc.z += v.z * wj; acc.w += v.w * wj;
        }
    }

    float4 av = ((const float4*)a)[lane];
    float4 p;
    p.x = acc.x >= 0.f ? acc.x : av.x * acc.x;
    p.y = acc.y >= 0.f ? acc.y : av.y * acc.y;
    p.z = acc.z >= 0.f ? acc.z : av.z * acc.z;
    p.w = acc.w >= 0.f ? acc.w : av.w * acc.w;

    if (mode == 0) {
        float4 sk = ((const float4*)skip_io)[node * 32 + lane];
        ((float4*)skip_io)[node * 32 + lane] =
            make_float4(sk.x + p.x, sk.y + p.y, sk.z + p.z, sk.w + p.w);
    } else {
        ((float4*)out)[node * 32 + lane] = p;
    }
}

extern "C" void kernel_launch(void* const* d_in, const int* in_sizes, int n_in,
                              void* d_out, int out_size) {
    const float* x  = (const float*)d_in[0];
    const int*   ei = (const int*)d_in[1];
    const float* W0 = (const float*)d_in[2];
    const float* b0 = (const float*)d_in[3];
    const float* W1 = (const float*)d_in[4];
    const float* b1 = (const float*)d_in[5];
    const float* Ws = (const float*)d_in[6];
    const float* bs = (const float*)d_in[7];
    const float* a  = (const float*)d_in[8];
    float* out = (float*)d_out;

    const int4* src4 = (const int4*)ei;
    const int4* dst4 = (const int4*)(ei + NE);

    float *t, *skip;
    __nv_bfloat16 *bth, *btl;
    cudaGetSymbolAddress((void**)&t, g_t);
    cudaGetSymbolAddress((void**)&skip, g_skip);
    cudaGetSymbolAddress((void**)&bth, g_bth);
    cudaGetSymbolAddress((void**)&btl, g_btl);

    cudaFuncSetAttribute(k_tgemm, cudaFuncAttributeMaxDynamicSharedMemorySize, TG_SMEM);

    const int TG_GRID = (NN + 127) / 128;  // 391
    const int GATHER_GRID = (NN * 32 + 255) / 256;
    const int E4 = NE / 4;
    const int MAT = C * C;

    // 10 launches; index 3 (ncu capture slot) = first tensor GEMM
    k_deg_count<<<(E4 + 255) / 256, 256>>>(dst4);                          // 0
    k_scan_a<<<NB, 256>>>();                                               // 1
    k_wsplit<<<(3 * MAT + 255) / 256, 256>>>(W0, W1, Ws);                  // 2

    k_tgemm<<<TG_GRID, 256, TG_SMEM>>>(x, bth + 2 * MAT, btl + 2 * MAT,
                                       bs, skip);                          // 3: skip = x@Ws+bs [ncu]
    k_tgemm<<<TG_GRID, 256, TG_SMEM>>>(x, bth, btl, nullptr, t);           // 4: t = x@W0

    k_scan_c<<<NB, 256>>>();                                               // 5
    k_bucket<<<(E4 + 255) / 256, 256>>>(src4, dst4);                       // 6 (re-zeros g_cnt)
    k_gather<<<GATHER_GRID, 256>>>(t, b0, a, skip, nullptr, 0);            // 7: skip = u

    k_tgemm<<<TG_GRID, 256, TG_SMEM>>>(skip, bth + MAT, btl + MAT,
                                       nullptr, t);                        // 8: t = u@W1
    k_gather<<<GATHER_GRID, 256>>>(t, b1, a, nullptr, out, 1);             // 9: out
}

// round 17
// speedup vs baseline: 1.5899x; 1.0513x over previous
#include <cuda_runtime.h>
#include <cuda_bf16.h>

#define NN 50000
#define NE 600000
#define C  128
#define NB ((NN + 255) / 256)   // 196 scan blocks

// ---------------- scratch (static __device__, zero-initialized at load) ----------------
__device__ int   g_cnt[NN];      // stays zero between pipeline runs (bucket re-zeros)
__device__ int   g_off[NN + 1];
__device__ int   g_cur[NN];
__device__ int   g_bsum[NB];
__device__ int   g_csrc[NE];
__device__ float g_dis[NN];
__device__ float g_t[NN * C];
__device__ float g_skip[NN * C];
__device__ __nv_bfloat16 g_bth[3 * C * C];  // [mat][n][k] = hi(W[k][n])
__device__ __nv_bfloat16 g_btl[3 * C * C];  // [mat][n][k] = lo(W[k][n])

// ---------------- fused: degree count (edge blocks) + W split (tail blocks) ----------------
#define EB ((NE / 4 + 255) / 256)          // 586 edge blocks
#define WSPLIT_BLOCKS ((3 * C * C) / 256)  // 192
__global__ void k_deg_wsplit(const int4* __restrict__ dst4, const float* __restrict__ W0,
                             const float* __restrict__ W1, const float* __restrict__ Ws) {
    int b = blockIdx.x;
    if (b < EB) {
        int i = b * 256 + threadIdx.x;
        if (i < NE / 4) {
            int4 d = dst4[i];
            atomicAdd(&g_cnt[d.x], 1);
            atomicAdd(&g_cnt[d.y], 1);
            atomicAdd(&g_cnt[d.z], 1);
            atomicAdd(&g_cnt[d.w], 1);
        }
    } else {
        int i = (b - EB) * 256 + threadIdx.x;   // < 3*C*C
        int mat = i >> 14, e = i & (C * C - 1);
        int n = e & 127, k = e >> 7;
        const float* W = (mat == 0) ? W0 : (mat == 1) ? W1 : Ws;
        float w = W[k * C + n];
        __nv_bfloat16 h = __float2bfloat16(w);
        __nv_bfloat16 l = __float2bfloat16(w - __bfloat162float(h));
        int dst = mat * C * C + n * C + k;
        g_bth[dst] = h;
        g_btl[dst] = l;
    }
}
__global__ void k_scan_a() {
    __shared__ int s[256];
    int tid = threadIdx.x;
    int i = blockIdx.x * 256 + tid;
    int v = (i < NN) ? g_cnt[i] : 0;
    s[tid] = v;
    __syncthreads();
    for (int d = 1; d < 256; d <<= 1) {
        int tv = 0;
        if (tid >= d) tv = s[tid - d];
        __syncthreads();
        if (tid >= d) s[tid] += tv;
        __syncthreads();
    }
    if (i < NN) g_off[i] = s[tid] - v;  // exclusive, block-local
    if (tid == 255) g_bsum[blockIdx.x] = s[255];
}
__global__ void k_scan_c() {
    __shared__ int red[256];
    int tid = threadIdx.x, bid = blockIdx.x;
    red[tid] = (tid < bid && tid < NB) ? g_bsum[tid] : 0;
    __syncthreads();
    for (int d = 128; d > 0; d >>= 1) {
        if (tid < d) red[tid] += red[tid + d];
        __syncthreads();
    }
    int base = red[0];
    int i = bid * 256 + tid;
    if (i < NN) {
        int o = g_off[i] + base;
        g_off[i] = o;
        g_cur[i] = o;
        g_dis[i] = rsqrtf((float)(g_cnt[i] + 1));  // +1 self loop
    }
    if (i == 0) g_off[NN] = NE;
}
__global__ void k_bucket(const int4* __restrict__ src4, const int4* __restrict__ dst4) {
    int i = blockIdx.x * blockDim.x + threadIdx.x;
    if (i < NE / 4) {
        int4 s = src4[i];
        int4 d = dst4[i];
        int p;
        p = atomicAdd(&g_cur[d.x], 1); g_csrc[p] = s.x;
        p = atomicAdd(&g_cur[d.y], 1); g_csrc[p] = s.y;
        p = atomicAdd(&g_cur[d.z], 1); g_csrc[p] = s.z;
        p = atomicAdd(&g_cur[d.w], 1); g_csrc[p] = s.w;
    }
    if (i < NN / 4) ((int4*)g_cnt)[i] = make_int4(0, 0, 0, 0);
}

// ================= bf16-split GEMM on mma.sync + ldmatrix =================
// A (hi/lo) resident full-K (TS=136); B staged per K=64 half (TSS=72) as bf16 copies.
// 104KB smem -> 2 CTA/SM. Warp tile 32r x 64c, ldmatrix.x4 fragments.
// Dual variant: one A staging, two B passes (mat0 -> out0+bias0, mat1 -> out1).

#define TS  136
#define TSS 72
#define A_ELEMS (128 * TS)
#define B_ELEMS (128 * TSS)
#define TG_SMEM ((2 * A_ELEMS + 2 * B_ELEMS) * 2)   // 106496 bytes

__device__ __forceinline__ unsigned s2u(const void* p) {
    unsigned a;
    asm("{ .reg .u64 t; cvta.to.shared.u64 t, %1; cvt.u32.u64 %0, t; }" : "=r"(a) : "l"(p));
    return a;
}
__device__ __forceinline__ void mma_bf16(float* d, const unsigned* a,
                                         unsigned b0, unsigned b1) {
    asm volatile(
        "mma.sync.aligned.m16n8k16.row.col.f32.bf16.bf16.f32 "
        "{%0,%1,%2,%3}, {%4,%5,%6,%7}, {%8,%9}, {%0,%1,%2,%3};"
        : "+f"(d[0]), "+f"(d[1]), "+f"(d[2]), "+f"(d[3])
        : "r"(a[0]), "r"(a[1]), "r"(a[2]), "r"(a[3]), "r"(b0), "r"(b1));
}
__device__ __forceinline__ void ldm4(unsigned* r, unsigned addr) {
    asm volatile("ldmatrix.sync.aligned.m8n8.x4.shared.b16 {%0,%1,%2,%3}, [%4];"
                 : "=r"(r[0]), "=r"(r[1]), "=r"(r[2]), "=r"(r[3]) : "r"(addr));
}

struct TGCtx {
    __nv_bfloat16 *AH, *AL, *BH, *BL;
    unsigned AHu, ALu, BHu, BLu;
    int r0, c0, lrow, lk, aoff, boff, row0, tid;
};

__device__ __forceinline__ void tg_stage_A(TGCtx& cx, const float* in) {
    for (int e = cx.tid; e < 8192; e += 256) {   // r = e>>6, c = 2*(e&63)
        int r = e >> 6, c = (e & 63) << 1;
        int gr = cx.row0 + r;
        float2 v = (gr < NN) ? *(const float2*)&in[gr * C + c] : make_float2(0.f, 0.f);
        __nv_bfloat162 h = __floats2bfloat162_rn(v.x, v.y);
        float2 hf = __bfloat1622float2(h);
        __nv_bfloat162 l = __floats2bfloat162_rn(v.x - hf.x, v.y - hf.y);
        *(__nv_bfloat162*)&cx.AH[r * TS + c] = h;
        *(__nv_bfloat162*)&cx.AL[r * TS + c] = l;
    }
}

// one full-K pass for one weight matrix; acc zeroed inside; result stored
__device__ __forceinline__ void tg_pass(TGCtx& cx, const __nv_bfloat16* bth,
                                        const __nv_bfloat16* btl, const float* bias,
                                        float* out) {
    float acc[2][8][4];
#pragma unroll
    for (int m = 0; m < 2; m++)
#pragma unroll
        for (int nt = 0; nt < 8; nt++)
#pragma unroll
            for (int j = 0; j < 4; j++) acc[m][nt][j] = 0.f;

#pragma unroll 1
    for (int ks = 0; ks < 2; ks++) {
        int k0 = ks * 64;
        __syncthreads();  // prior compute (this or previous pass) done before overwrite
        for (int e = cx.tid; e < 2048; e += 256) {
            int tile = e >> 10, rem = e & 1023;
            int n = rem >> 3, ch = (rem & 7) << 3;
            const __nv_bfloat16* src = (tile ? btl : bth) + n * C + k0 + ch;
            __nv_bfloat16* dst = (tile ? cx.BL : cx.BH) + n * TSS + ch;
            *(int4*)dst = *(const int4*)src;
        }
        __syncthreads();

#pragma unroll
        for (int kc = 0; kc < 4; kc++) {
            int kbA = k0 + kc * 16;
            int kbB = kc * 16;
            unsigned a0o = 2u * (unsigned)(cx.r0 * TS + kbA + cx.aoff);
            unsigned a1o = 2u * (unsigned)((cx.r0 + 16) * TS + kbA + cx.aoff);
            unsigned aH0[4], aH1[4], aL0[4], aL1[4];
            ldm4(aH0, cx.AHu + a0o);
            ldm4(aH1, cx.AHu + a1o);
            ldm4(aL0, cx.ALu + a0o);
            ldm4(aL1, cx.ALu + a1o);
#pragma unroll
            for (int np = 0; np < 4; np++) {
                unsigned bo = 2u * (unsigned)((cx.c0 + np * 16) * TSS + kbB + cx.boff);
                unsigned bh[4], bl[4];
                ldm4(bh, cx.BHu + bo);
                ldm4(bl, cx.BLu + bo);
                int nt0 = np * 2, nt1 = np * 2 + 1;
                mma_bf16(acc[0][nt0], aH0, bh[0], bh[1]);
                mma_bf16(acc[0][nt0], aH0, bl[0], bl[1]);
                mma_bf16(acc[0][nt0], aL0, bh[0], bh[1]);
                mma_bf16(acc[0][nt1], aH0, bh[2], bh[3]);
                mma_bf16(acc[0][nt1], aH0, bl[2], bl[3]);
                mma_bf16(acc[0][nt1], aL0, bh[2], bh[3]);
                mma_bf16(acc[1][nt0], aH1, bh[0], bh[1]);
                mma_bf16(acc[1][nt0], aH1, bl[0], bl[1]);
                mma_bf16(acc[1][nt0], aL1, bh[0], bh[1]);
                mma_bf16(acc[1][nt1], aH1, bh[2], bh[3]);
                mma_bf16(acc[1][nt1], aH1, bl[2], bl[3]);
                mma_bf16(acc[1][nt1], aL1, bh[2], bh[3]);
            }
        }
    }

#pragma unroll
    for (int m = 0; m < 2; m++) {
        int gr0 = cx.row0 + cx.r0 + m * 16 + cx.lrow;
        int gr1 = gr0 + 8;
#pragma unroll
        for (int nt = 0; nt < 8; nt++) {
            int col = cx.c0 + nt * 8 + cx.lk;
            float bx = 0.f, by = 0.f;
            if (bias) { bx = bias[col]; by = bias[col + 1]; }
            if (gr0 < NN)
                *(float2*)&out[gr0 * C + col] =
                    make_float2(acc[m][nt][0] + bx, acc[m][nt][1] + by);
            if (gr1 < NN)
                *(float2*)&out[gr1 * C + col] =
                    make_float2(acc[m][nt][2] + bx, acc[m][nt][3] + by);
        }
    }
}

__device__ __forceinline__ void tg_init(TGCtx& cx, __nv_bfloat16* ts) {
    cx.AH = ts;
    cx.AL = cx.AH + A_ELEMS;
    cx.BH = cx.AL + A_ELEMS;
    cx.BL = cx.BH + B_ELEMS;
    cx.tid = threadIdx.x;
    cx.row0 = blockIdx.x * 128;
    int wid = cx.tid >> 5, lane = cx.tid & 31;
    cx.r0 = (wid & 3) * 32;
    cx.c0 = (wid >> 2) * 64;
    cx.lrow = lane >> 2;
    cx.lk = (lane & 3) << 1;
    int mi = lane >> 3, rr = lane & 7;
    cx.aoff = ((mi & 1) * 8 + rr) * TS + (mi >> 1) * 8;
    cx.boff = ((mi >> 1) * 8 + rr) * TSS + (mi & 1) * 8;
    cx.AHu = s2u(cx.AH); cx.ALu = s2u(cx.AL);
    cx.BHu = s2u(cx.BH); cx.BLu = s2u(cx.BL);
}

// dual: skip = x@Ws + bs ; t = x@W0   (A staged once)
__global__ __launch_bounds__(256, 2) void k_tgemm_dual(
    const float* __restrict__ x,
    const __nv_bfloat16* __restrict__ bth, const __nv_bfloat16* __restrict__ btl,
    const float* __restrict__ bs, float* __restrict__ skip, float* __restrict__ t) {
    extern __shared__ __nv_bfloat16 ts[];
    TGCtx cx;
    tg_init(cx, ts);
    tg_stage_A(cx, x);
    const int MAT = C * C;
    tg_pass(cx, bth + 2 * MAT, btl + 2 * MAT, bs, skip);  // Ws
    tg_pass(cx, bth, btl, nullptr, t);                    // W0
}

// single: out = in @ W[mat] (+bias)
__global__ __launch_bounds__(256, 2) void k_tgemm(
    const float* __restrict__ in,
    const __nv_bfloat16* __restrict__ bth, const __nv_bfloat16* __restrict__ btl,
    const float* __restrict__ bias, float* __restrict__ out) {
    extern __shared__ __nv_bfloat16 ts[];
    TGCtx cx;
    tg_init(cx, ts);
    tg_stage_A(cx, in);
    tg_pass(cx, bth, btl, bias, out);
}

// ---------------- CSR gather: one warp per node, edge loop unrolled x4 ----------------
__global__ __launch_bounds__(256) void k_gather(const float* __restrict__ t,
                                                const float* __restrict__ b,
                                                const float* __restrict__ a,
                                                float* __restrict__ skip_io,
                                                float* __restrict__ out, int mode) {
    int node = (blockIdx.x * 256 + threadIdx.x) >> 5;
    int lane = threadIdx.x & 31;
    if (node >= NN) return;

    float di = g_dis[node];
    float d2 = di * di;
    float4 bv = ((const float4*)b)[lane];
    float4 tv = ((const float4*)t)[node * 32 + lane];
    float4 acc = make_float4(bv.x + tv.x * d2, bv.y + tv.y * d2,
                             bv.z + tv.z * d2, bv.w + tv.w * d2);

    int beg = g_off[node], end = g_off[node + 1];
    for (int base = beg; base < end; base += 32) {
        int idx = base + lane;
        int s = 0;
        float w = 0.f;
        if (idx < end) {
            s = g_csrc[idx];
            w = g_dis[s] * di;
        }
        int cnt = min(32, end - base);
        int j = 0;
        for (; j + 4 <= cnt; j += 4) {
            int s0 = __shfl_sync(0xffffffffu, s, j);
            int s1 = __shfl_sync(0xffffffffu, s, j + 1);
            int s2 = __shfl_sync(0xffffffffu, s, j + 2);
            int s3 = __shfl_sync(0xffffffffu, s, j + 3);
            float w0 = __shfl_sync(0xffffffffu, w, j);
            float w1 = __shfl_sync(0xffffffffu, w, j + 1);
            float w2 = __shfl_sync(0xffffffffu, w, j + 2);
            float w3 = __shfl_sync(0xffffffffu, w, j + 3);
            float4 v0 = ((const float4*)t)[s0 * 32 + lane];
            float4 v1 = ((const float4*)t)[s1 * 32 + lane];
            float4 v2 = ((const float4*)t)[s2 * 32 + lane];
            float4 v3 = ((const float4*)t)[s3 * 32 + lane];
            acc.x += v0.x * w0; acc.y += v0.y * w0; acc.z += v0.z * w0; acc.w += v0.w * w0;
            acc.x += v1.x * w1; acc.y += v1.y * w1; acc.z += v1.z * w1; acc.w += v1.w * w1;
            acc.x += v2.x * w2; acc.y += v2.y * w2; acc.z += v2.z * w2; acc.w += v2.w * w2;
            acc.x += v3.x * w3; acc.y += v3.y * w3; acc.z += v3.z * w3; acc.w += v3.w * w3;
        }
        for (; j < cnt; j++) {
            int sj = __shfl_sync(0xffffffffu, s, j);
            float wj = __shfl_sync(0xffffffffu, w, j);
            float4 v = ((const float4*)t)[sj * 32 + lane];
            acc.x += v.x * wj; acc.y += v.y * wj; acc.z += v.z * wj; acc.w += v.w * wj;
        }
    }

    float4 av = ((const float4*)a)[lane];
    float4 p;
    p.x = acc.x >= 0.f ? acc.x : av.x * acc.x;
    p.y = acc.y >= 0.f ? acc.y : av.y * acc.y;
    p.z = acc.z >= 0.f ? acc.z : av.z * acc.z;
    p.w = acc.w >= 0.f ? acc.w : av.w * acc.w;

    if (mode == 0) {
        float4 sk = ((const float4*)skip_io)[node * 32 + lane];
        ((float4*)skip_io)[node * 32 + lane] =
            make_float4(sk.x + p.x, sk.y + p.y, sk.z + p.z, sk.w + p.w);
    } else {
        ((float4*)out)[node * 32 + lane] = p;
    }
}

extern "C" void kernel_launch(void* const* d_in, const int* in_sizes, int n_in,
                              void* d_out, int out_size) {
    const float* x  = (const float*)d_in[0];
    const int*   ei = (const int*)d_in[1];
    const float* W0 = (const float*)d_in[2];
    const float* b0 = (const float*)d_in[3];
    const float* W1 = (const float*)d_in[4];
    const float* b1 = (const float*)d_in[5];
    const float* Ws = (const float*)d_in[6];
    const float* bs = (const float*)d_in[7];
    const float* a  = (const float*)d_in[8];
    float* out = (float*)d_out;

    const int4* src4 = (const int4*)ei;
    const int4* dst4 = (const int4*)(ei + NE);

    float *t, *skip;
    __nv_bfloat16 *bth, *btl;
    cudaGetSymbolAddress((void**)&t, g_t);
    cudaGetSymbolAddress((void**)&skip, g_skip);
    cudaGetSymbolAddress((void**)&bth, g_bth);
    cudaGetSymbolAddress((void**)&btl, g_btl);

    cudaFuncSetAttribute(k_tgemm_dual, cudaFuncAttributeMaxDynamicSharedMemorySize, TG_SMEM);
    cudaFuncSetAttribute(k_tgemm, cudaFuncAttributeMaxDynamicSharedMemorySize, TG_SMEM);

    const int TG_GRID = (NN + 127) / 128;  // 391
    const int GATHER_GRID = (NN * 32 + 255) / 256;
    const int E4 = NE / 4;
    const int MAT = C * C;

    // 8 launches; index 3 (ncu capture slot) = dual tensor GEMM
    k_deg_wsplit<<<EB + WSPLIT_BLOCKS, 256>>>(dst4, W0, W1, Ws);           // 0
    k_scan_a<<<NB, 256>>>();                                               // 1
    k_scan_c<<<NB, 256>>>();                                               // 2

    k_tgemm_dual<<<TG_GRID, 256, TG_SMEM>>>(x, bth, btl, bs, skip, t);     // 3 [ncu]

    k_bucket<<<(E4 + 255) / 256, 256>>>(src4, dst4);                       // 4 (re-zeros g_cnt)
    k_gather<<<GATHER_GRID, 256>>>(t, b0, a, skip, nullptr, 0);            // 5: skip = u

    k_tgemm<<<TG_GRID, 256, TG_SMEM>>>(skip, bth + MAT, btl + MAT,
                                       nullptr, t);                        // 6: t = u@W1
    k_gather<<<GATHER_GRID, 256>>>(t, b1, a, nullptr, out, 1);             // 7: out
}